// round 3
// baseline (speedup 1.0000x reference)
#include <cuda_runtime.h>
#include <cstdint>

typedef unsigned long long ull;

// ---- packed f32x2 helpers (sm_103a) ----
__device__ __forceinline__ ull ffma2(ull a, ull b, ull c) {
    ull d;
    asm("fma.rn.f32x2 %0, %1, %2, %3;" : "=l"(d) : "l"(a), "l"(b), "l"(c));
    return d;
}
__device__ __forceinline__ ull fmul2(ull a, ull b) {
    ull d;
    asm("mul.rn.f32x2 %0, %1, %2;" : "=l"(d) : "l"(a), "l"(b));
    return d;
}
__device__ __forceinline__ ull fadd2(ull a, ull b) {
    ull d;
    asm("add.rn.f32x2 %0, %1, %2;" : "=l"(d) : "l"(a), "l"(b));
    return d;
}
__device__ __forceinline__ ull pack2(float lo, float hi) {
    ull d;
    asm("mov.b64 %0, {%1, %2};" : "=l"(d) : "f"(lo), "f"(hi));
    return d;
}
__device__ __forceinline__ ull dup2(float v) { return pack2(v, v); }
__device__ __forceinline__ float2 unpack2(ull v) {
    float lo, hi;
    asm("mov.b64 {%0, %1}, %2;" : "=f"(lo), "=f"(hi) : "l"(v));
    return make_float2(lo, hi);
}

// ---- mbarrier helpers ----
__device__ __forceinline__ uint32_t smem_u32(const void* p) {
    uint32_t a;
    asm("{ .reg .u64 t; cvta.to.shared.u64 t, %1; cvt.u32.u64 %0, t; }"
        : "=r"(a) : "l"(p));
    return a;
}
__device__ __forceinline__ void mbar_init(uint32_t addr, uint32_t count) {
    asm volatile("mbarrier.init.shared.b64 [%0], %1;" :: "r"(addr), "r"(count) : "memory");
}
__device__ __forceinline__ void mbar_arrive(uint32_t addr) {
    asm volatile("mbarrier.arrive.release.cta.shared::cta.b64 _, [%0];"
                 :: "r"(addr) : "memory");
}
__device__ __forceinline__ void mbar_wait(uint32_t addr, uint32_t parity) {
    asm volatile(
        "{\n\t"
        ".reg .pred P;\n\t"
        "WAIT_%=:\n\t"
        "mbarrier.try_wait.parity.acquire.cta.shared::cta.b64 P, [%0], %1, 0x989680;\n\t"
        "@!P bra WAIT_%=;\n\t"
        "}" :: "r"(addr), "r"(parity) : "memory");
}

constexpr int D_DIM        = 1024;
constexpr int THREADS      = 256;
constexpr int NWARP        = 8;
constexpr int ROWS_PER_BLK = 64;
constexpr int BATCH        = 8;                     // rows per mbarrier batch
constexpr int NBATCH       = ROWS_PER_BLK / BATCH;  // 8 (== NWARP, rotation is even)
constexpr int NGRP         = 32;                    // 8-lane groups over 256 threads
constexpr int SLOTS        = BATCH * 3;             // 24 (row, f32x2-pair)
constexpr int PSTRIDE      = SLOTS + 1;             // pad to dodge bank conflicts

// compute 4 rows from xv[0..3], 3-round butterfly, STS group sums
__device__ __forceinline__ void compute4(const float4* xv, const ull wp[4][3],
                                         ull* pbase, int slotbase,
                                         int lane, int warp) {
    #pragma unroll
    for (int u = 0; u < 4; ++u) {
        ull xx = dup2(xv[u].x);
        ull a0 = fmul2(xx, wp[0][0]);
        ull a1 = fmul2(xx, wp[0][1]);
        ull a2 = fmul2(xx, wp[0][2]);
        xx = dup2(xv[u].y);
        a0 = ffma2(xx, wp[1][0], a0);
        a1 = ffma2(xx, wp[1][1], a1);
        a2 = ffma2(xx, wp[1][2], a2);
        xx = dup2(xv[u].z);
        a0 = ffma2(xx, wp[2][0], a0);
        a1 = ffma2(xx, wp[2][1], a1);
        a2 = ffma2(xx, wp[2][2], a2);
        xx = dup2(xv[u].w);
        a0 = ffma2(xx, wp[3][0], a0);
        a1 = ffma2(xx, wp[3][1], a1);
        a2 = ffma2(xx, wp[3][2], a2);

        // reduce 8-lane groups (32 consecutive columns each)
        a0 = fadd2(a0, __shfl_xor_sync(0xffffffffu, a0, 1));
        a1 = fadd2(a1, __shfl_xor_sync(0xffffffffu, a1, 1));
        a2 = fadd2(a2, __shfl_xor_sync(0xffffffffu, a2, 1));
        a0 = fadd2(a0, __shfl_xor_sync(0xffffffffu, a0, 2));
        a1 = fadd2(a1, __shfl_xor_sync(0xffffffffu, a1, 2));
        a2 = fadd2(a2, __shfl_xor_sync(0xffffffffu, a2, 2));
        a0 = fadd2(a0, __shfl_xor_sync(0xffffffffu, a0, 4));
        a1 = fadd2(a1, __shfl_xor_sync(0xffffffffu, a1, 4));
        a2 = fadd2(a2, __shfl_xor_sync(0xffffffffu, a2, 4));

        if ((lane & 7) == 0) {
            const int g = warp * 4 + (lane >> 3);     // 0..31
            ull* dst = pbase + g * PSTRIDE + slotbase + u * 3;
            dst[0] = a0; dst[1] = a1; dst[2] = a2;
        }
    }
}

__global__ void __launch_bounds__(THREADS, 3)
q6_kernel(const float* __restrict__ x,
          const float* __restrict__ W,
          const float* __restrict__ proto,
          const float* __restrict__ hs,
          float* __restrict__ out)
{
    __shared__ ull   part[2][NGRP * PSTRIDE];
    __shared__ float pn[8][6];
    __shared__ float s3_sh;
    __shared__ __align__(8) ull mbar[4];   // [0,1]=full[buf], [2,3]=empty[buf]

    const int tid  = threadIdx.x;
    const int lane = tid & 31;
    const int warp = tid >> 5;
    const int col  = tid * 4;          // this thread owns columns [col, col+4)

    // ---- one-time block init ----
    if (tid < 8) {
        float v[6]; float ss = 0.f;
        #pragma unroll
        for (int k = 0; k < 6; ++k) { v[k] = proto[tid * 6 + k]; ss += v[k] * v[k]; }
        float n = fmaxf(sqrtf(ss), 1e-12f);
        #pragma unroll
        for (int k = 0; k < 6; ++k) pn[tid][k] = v[k] / n;
    }
    if (tid == 8) s3_sh = 3.0f * hs[0];   // softmax(-hs*(6-6d)/2) == softmax(3*hs*d)
    if (tid == 0) {
        mbar_init(smem_u32(&mbar[0]), NWARP);  // full[0]
        mbar_init(smem_u32(&mbar[1]), NWARP);  // full[1]
        mbar_init(smem_u32(&mbar[2]), 1);      // empty[0]
        mbar_init(smem_u32(&mbar[3]), 1);      // empty[1]
    }
    __syncthreads();

    // ---- W slice: 4 columns, packed (k0,k1),(k2,k3),(k4,k5) ----
    ull wp[4][3];
    {
        float4 w4[6];
        #pragma unroll
        for (int k = 0; k < 6; ++k)
            w4[k] = *reinterpret_cast<const float4*>(W + k * D_DIM + col);
        #pragma unroll
        for (int p = 0; p < 3; ++p) {
            wp[0][p] = pack2(w4[2*p].x, w4[2*p+1].x);
            wp[1][p] = pack2(w4[2*p].y, w4[2*p+1].y);
            wp[2][p] = pack2(w4[2*p].z, w4[2*p+1].z);
            wp[3][p] = pack2(w4[2*p].w, w4[2*p+1].w);
        }
    }

    const int    rowbase = blockIdx.x * ROWS_PER_BLK;
    const float* xp      = x + (size_t)rowbase * D_DIM + col;

    // preload rows 0..3 (pipeline primer)
    float4 xa[4], xb[4];
    #pragma unroll
    for (int u = 0; u < 4; ++u)
        xa[u] = __ldcs(reinterpret_cast<const float4*>(xp + (size_t)u * D_DIM));

    #pragma unroll 1
    for (int b = 0; b < NBATCH; ++b) {
        const int buf = b & 1;
        ull* pbase = part[buf];

        // buffer reuse gate: reducer of batch b-2 must have drained part[buf]
        if (b >= 2) mbar_wait(smem_u32(&mbar[2 + buf]), ((b - 2) >> 1) & 1);

        const float* xrow = xp + (size_t)(b * BATCH) * D_DIM;

        // prefetch rows b*8+4..7 while computing rows b*8..+3
        #pragma unroll
        for (int u = 0; u < 4; ++u)
            xb[u] = __ldcs(reinterpret_cast<const float4*>(xrow + (size_t)(4 + u) * D_DIM));
        compute4(xa, wp, pbase, 0, lane, warp);

        // prefetch next batch's rows 0..3 while computing rows b*8+4..7
        if (b + 1 < NBATCH) {
            #pragma unroll
            for (int u = 0; u < 4; ++u)
                xa[u] = __ldcs(reinterpret_cast<const float4*>(xrow + (size_t)(8 + u) * D_DIM));
        }
        compute4(xb, wp, pbase, 12, lane, warp);

        __syncwarp();
        if (lane == 0) mbar_arrive(smem_u32(&mbar[buf]));   // full[buf]

        // ---- rotating reducer: warp b handles batch b's 8 rows ----
        if (warp == b) {
            mbar_wait(smem_u32(&mbar[buf]), (b >> 1) & 1);  // all 8 warps' STS visible

            ull sum = 0ull;
            if (lane < SLOTS) {
                ull s0 = 0ull, s1 = 0ull, s2 = 0ull, s3v = 0ull;
                #pragma unroll
                for (int g = 0; g < NGRP; g += 4) {
                    s0  = fadd2(s0,  pbase[(g + 0) * PSTRIDE + lane]);
                    s1  = fadd2(s1,  pbase[(g + 1) * PSTRIDE + lane]);
                    s2  = fadd2(s2,  pbase[(g + 2) * PSTRIDE + lane]);
                    s3v = fadd2(s3v, pbase[(g + 3) * PSTRIDE + lane]);
                }
                sum = fadd2(fadd2(s0, s1), fadd2(s2, s3v));
            }
            // transpose: lane r (<8) gathers its row's 3 pairs from lanes 3r..3r+2
            ull z0 = __shfl_sync(0xffffffffu, sum, lane * 3 + 0);
            ull z1 = __shfl_sync(0xffffffffu, sum, lane * 3 + 1);
            ull z2 = __shfl_sync(0xffffffffu, sum, lane * 3 + 2);

            __syncwarp();
            if (lane == 0) mbar_arrive(smem_u32(&mbar[2 + buf]));  // empty[buf]

            // ---- epilogue (SIMT; lanes 0..7 meaningful) ----
            float z[6];
            {
                float2 v0 = unpack2(z0), v1 = unpack2(z1), v2 = unpack2(z2);
                z[0] = v0.x; z[1] = v0.y; z[2] = v1.x;
                z[3] = v1.y; z[4] = v2.x; z[5] = v2.y;
            }
            float ss = 0.f;
            #pragma unroll
            for (int k = 0; k < 6; ++k) {
                float e2 = __expf(2.0f * z[k]);        // tanh = 1 - 2/(e^2x + 1)
                z[k] = 1.0f - __fdividef(2.0f, e2 + 1.0f);
                ss += z[k] * z[k];
            }
            const float sc = __fdividef(s3_sh, fmaxf(sqrtf(ss), 1e-6f));

            float e[8]; float esum = 0.f;
            #pragma unroll
            for (int p = 0; p < 8; ++p) {
                float d = 0.f;
                #pragma unroll
                for (int k = 0; k < 6; ++k) d += z[k] * pn[p][k];
                e[p] = __expf(sc * d);
                esum += e[p];
            }
            const float rs = __fdividef(1.0f, esum);
            if (lane < 8) {
                const int row = rowbase + b * BATCH + lane;
                float4* op = reinterpret_cast<float4*>(out + (size_t)row * 8);
                op[0] = make_float4(e[0]*rs, e[1]*rs, e[2]*rs, e[3]*rs);
                op[1] = make_float4(e[4]*rs, e[5]*rs, e[6]*rs, e[7]*rs);
            }
        }
    }
}

extern "C" void kernel_launch(void* const* d_in, const int* in_sizes, int n_in,
                              void* d_out, int out_size) {
    const float* x     = (const float*)d_in[0];
    const float* W     = (const float*)d_in[1];
    const float* proto = (const float*)d_in[2];
    const float* hs    = (const float*)d_in[3];
    float* out = (float*)d_out;

    const int n_rows = in_sizes[0] / D_DIM;      // 32768
    const int grid   = n_rows / ROWS_PER_BLK;    // 512
    q6_kernel<<<grid, THREADS>>>(x, W, proto, hs, out);
}